// round 16
// baseline (speedup 1.0000x reference)
#include <cuda_runtime.h>
#include <cstdint>
#include <cstddef>

// Bihomogeneous_k3 — FINAL (converged, rounds 0-15).
// 92.2us = 6.96 TB/s effective write bandwidth (87% of 8TB/s spec), at the
// HBM3e pure-write ceiling: profiled HBM pinned at 5.9-6.1 TB/s across all
// variants spanning issue 63-87% / L1 66-85%, with zero duration effect
// (R12 controlled experiment). Output is 642MB mandatory write-once traffic.
//
// Design: warp-per-row (natural mapping -> DRAM page locality), 35 complex
// monomials staged in smem, fused re+im per pair (one operand fetch -> two
// outputs), compile-time breakpoint chains for (p,q), and a per-row phase
// shift so every main-loop re-store is a 128B-aligned single-wavefront STG.

#define NVAR 5
#define NM 35
#define NPAIR 630
#define NCOL 1225
#define WPB 8
#define NGRP 20

__host__ __device__ constexpr int off_of(int p) { return p * (71 - p) / 2; }
__host__ __device__ constexpr int p_of(int s) {
    int p = 0;
    while (p < NM - 1 && off_of(p + 1) <= s) p++;
    return p;
}
__host__ __device__ constexpr int cmin(int a, int b) { return a < b ? a : b; }

template<int... I> struct iseq {};
template<int N, int... I> struct make_iseq : make_iseq<N - 1, N - 1, I...> {};
template<int... I> struct make_iseq<0, I...> { using type = iseq<I...>; };

// p for pair index s: pmin + count of compile-time breakpoints passed
template<int PMIN, int... J>
__device__ __forceinline__ int p_from_s(int s, iseq<J...>) {
    int p = PMIN;
    ((p += (s >= off_of(PMIN + 1 + J)) ? 1 : 0), ...);
    return p;
}

template<int G>
__device__ __forceinline__ void do_group(const float2* __restrict__ zz,
                                         float* __restrict__ orow,
                                         float* __restrict__ orowi,
                                         int c0, int lane) {
    const int s = c0 + 32 * G + lane;          // c0 in [0,31]: aligned schedule
    constexpr int smax_static = 32 * G + 62;   // max possible s in this group
    if constexpr (smax_static >= NPAIR) {
        if (s >= NPAIR) return;
    }
    constexpr int pmin = p_of(32 * G);
    constexpr int pmax = p_of(cmin(smax_static, NPAIR - 1));

    const int p = p_from_s<pmin>(s, typename make_iseq<pmax - pmin>::type{});
    const int q = s + p - ((p * (71 - p)) >> 1);   // s - off(p) + p

    const float2 a = zz[p];                        // broadcast: 1 wf
    const float2 b = zz[q];                        // consecutive q: 2 wf
    __stcs(orow + s, a.x * b.x + a.y * b.y);       // 128B-aligned store: 1 wf
    if (q > p)                                     // strict pair -> im column
        __stcs(orowi + (s - p), a.y * b.x - a.x * b.y);
}

template<int... G>
__device__ __forceinline__ void all_groups(iseq<G...>, const float2* __restrict__ zz,
                                           float* __restrict__ orow,
                                           float* __restrict__ orowi, int c0, int lane) {
    (do_group<G>(zz, orow, orowi, c0, lane), ...);
}

// monomial index table for stage 1 (2 warp-iterations, negligible traffic)
struct TabM { ushort ijk[40]; };
static constexpr TabM make_tabm() {
    TabM t{};
    int m = 0;
    for (int i = 0; i < NVAR; i++)
        for (int j = i; j < NVAR; j++)
            for (int k = j; k < NVAR; k++) {
                t.ijk[m] = (ushort)(i | (j << 4) | (k << 8));
                m++;
            }
    return t;
}
__device__ const TabM g_tabm = make_tabm();

__global__ void __launch_bounds__(WPB * 32)
bihom_k3_kernel(const float* __restrict__ z_re,
                const float* __restrict__ z_im,
                float* __restrict__ out, int B)
{
    const int warp = threadIdx.x >> 5;
    const int lane = threadIdx.x & 31;
    const int row  = blockIdx.x * WPB + warp;

    __shared__ float2 szz[WPB][NM + 1];
    __shared__ float  sz[WPB][2][NVAR + 3];

    if (row >= B) return;   // one row per warp: uniform exit

    // stage 0: row inputs into smem
    if (lane < NVAR) {
        sz[warp][0][lane] = z_re[row * NVAR + lane];
        sz[warp][1][lane] = z_im[row * NVAR + lane];
    }
    __syncwarp();

    // stage 1: 35 complex monomials z_i z_j z_k
    for (int mm = lane; mm < NM; mm += 32) {
        const unsigned v = g_tabm.ijk[mm];
        const int i = v & 15, j = (v >> 4) & 15, k = (v >> 8) & 15;
        const float ar = sz[warp][0][i], ai = sz[warp][1][i];
        const float br = sz[warp][0][j], bi = sz[warp][1][j];
        const float cr = sz[warp][0][k], ci = sz[warp][1][k];
        const float tr = ar * br - ai * bi;
        const float ti = ar * bi + ai * br;
        szz[warp][mm] = make_float2(tr * cr - ti * ci, tr * ci + ti * cr);
    }
    __syncwarp();

    // stage 2: phase so that (row*NCOL + c0) is 128B-aligned
    const int rowoff = row * NCOL;
    const int c0 = (-rowoff) & 31;

    float* __restrict__ orow  = out + (size_t)rowoff;
    float* __restrict__ orowi = orow + (NPAIR - 1);   // im col = 629 + s - p
    const float2* zz = szz[warp];

    // prologue: columns [0, c0). Here s < 31 < off(1)=35 -> p = 0, q = s.
    {
        const int s0 = c0 - 32 + lane;
        if (s0 >= 0) {
            const float2 a = zz[0];
            const float2 b = zz[s0];
            __stcs(orow + s0, a.x * b.x + a.y * b.y);
            if (s0 > 0)
                __stcs(orowi + s0, a.y * b.x - a.x * b.y);
        }
    }

    all_groups(typename make_iseq<NGRP>::type{}, zz, orow, orowi, c0, lane);
}

extern "C" void kernel_launch(void* const* d_in, const int* in_sizes, int n_in,
                              void* d_out, int out_size) {
    const float* z_re = (const float*)d_in[0];
    const float* z_im = (const float*)d_in[1];
    float* out = (float*)d_out;
    const int B = in_sizes[0] / NVAR;
    const int grid = (B + WPB - 1) / WPB;
    bihom_k3_kernel<<<grid, WPB * 32>>>(z_re, z_im, out, B);
}

// round 17
// speedup vs baseline: 1.0042x; 1.0042x over previous
#include <cuda_runtime.h>
#include <cstdint>
#include <cstddef>

// Bihomogeneous_k3 — FINAL (converged; rounds 0-16).
// 92.2us = 6.96 TB/s effective write bandwidth (87% of 8TB/s spec), at the
// HBM3e pure-write ceiling: profiled HBM pinned at 5.9-6.1 TB/s across all
// variants spanning issue 63-87% / L1 66-85%, with zero duration effect
// (R12 controlled experiment). Output is 642MB mandatory write-once traffic.
//
// Design: warp-per-row (natural mapping -> DRAM page locality), 35 complex
// monomials staged in smem, fused re+im per pair (one operand fetch -> two
// outputs), compile-time breakpoint chains for (p,q), and a per-row phase
// shift so every main-loop re-store is a 128B-aligned single-wavefront STG.

#define NVAR 5
#define NM 35
#define NPAIR 630
#define NCOL 1225
#define WPB 8
#define NGRP 20

__host__ __device__ constexpr int off_of(int p) { return p * (71 - p) / 2; }
__host__ __device__ constexpr int p_of(int s) {
    int p = 0;
    while (p < NM - 1 && off_of(p + 1) <= s) p++;
    return p;
}
__host__ __device__ constexpr int cmin(int a, int b) { return a < b ? a : b; }

template<int... I> struct iseq {};
template<int N, int... I> struct make_iseq : make_iseq<N - 1, N - 1, I...> {};
template<int... I> struct make_iseq<0, I...> { using type = iseq<I...>; };

// p for pair index s: pmin + count of compile-time breakpoints passed
template<int PMIN, int... J>
__device__ __forceinline__ int p_from_s(int s, iseq<J...>) {
    int p = PMIN;
    ((p += (s >= off_of(PMIN + 1 + J)) ? 1 : 0), ...);
    return p;
}

template<int G>
__device__ __forceinline__ void do_group(const float2* __restrict__ zz,
                                         float* __restrict__ orow,
                                         float* __restrict__ orowi,
                                         int c0, int lane) {
    const int s = c0 + 32 * G + lane;          // c0 in [0,31]: aligned schedule
    constexpr int smax_static = 32 * G + 62;   // max possible s in this group
    if constexpr (smax_static >= NPAIR) {
        if (s >= NPAIR) return;
    }
    constexpr int pmin = p_of(32 * G);
    constexpr int pmax = p_of(cmin(smax_static, NPAIR - 1));

    const int p = p_from_s<pmin>(s, typename make_iseq<pmax - pmin>::type{});
    const int q = s + p - ((p * (71 - p)) >> 1);   // s - off(p) + p

    const float2 a = zz[p];                        // broadcast: 1 wf
    const float2 b = zz[q];                        // consecutive q: 2 wf
    __stcs(orow + s, a.x * b.x + a.y * b.y);       // 128B-aligned store: 1 wf
    if (q > p)                                     // strict pair -> im column
        __stcs(orowi + (s - p), a.y * b.x - a.x * b.y);
}

template<int... G>
__device__ __forceinline__ void all_groups(iseq<G...>, const float2* __restrict__ zz,
                                           float* __restrict__ orow,
                                           float* __restrict__ orowi, int c0, int lane) {
    (do_group<G>(zz, orow, orowi, c0, lane), ...);
}

// monomial index table for stage 1 (2 warp-iterations, negligible traffic)
struct TabM { ushort ijk[40]; };
static constexpr TabM make_tabm() {
    TabM t{};
    int m = 0;
    for (int i = 0; i < NVAR; i++)
        for (int j = i; j < NVAR; j++)
            for (int k = j; k < NVAR; k++) {
                t.ijk[m] = (ushort)(i | (j << 4) | (k << 8));
                m++;
            }
    return t;
}
__device__ const TabM g_tabm = make_tabm();

__global__ void __launch_bounds__(WPB * 32)
bihom_k3_kernel(const float* __restrict__ z_re,
                const float* __restrict__ z_im,
                float* __restrict__ out, int B)
{
    const int warp = threadIdx.x >> 5;
    const int lane = threadIdx.x & 31;
    const int row  = blockIdx.x * WPB + warp;

    __shared__ float2 szz[WPB][NM + 1];
    __shared__ float  sz[WPB][2][NVAR + 3];

    if (row >= B) return;   // one row per warp: uniform exit

    // stage 0: row inputs into smem
    if (lane < NVAR) {
        sz[warp][0][lane] = z_re[row * NVAR + lane];
        sz[warp][1][lane] = z_im[row * NVAR + lane];
    }
    __syncwarp();

    // stage 1: 35 complex monomials z_i z_j z_k
    for (int mm = lane; mm < NM; mm += 32) {
        const unsigned v = g_tabm.ijk[mm];
        const int i = v & 15, j = (v >> 4) & 15, k = (v >> 8) & 15;
        const float ar = sz[warp][0][i], ai = sz[warp][1][i];
        const float br = sz[warp][0][j], bi = sz[warp][1][j];
        const float cr = sz[warp][0][k], ci = sz[warp][1][k];
        const float tr = ar * br - ai * bi;
        const float ti = ar * bi + ai * br;
        szz[warp][mm] = make_float2(tr * cr - ti * ci, tr * ci + ti * cr);
    }
    __syncwarp();

    // stage 2: phase so that (row*NCOL + c0) is 128B-aligned
    const int rowoff = row * NCOL;
    const int c0 = (-rowoff) & 31;

    float* __restrict__ orow  = out + (size_t)rowoff;
    float* __restrict__ orowi = orow + (NPAIR - 1);   // im col = 629 + s - p
    const float2* zz = szz[warp];

    // prologue: columns [0, c0). Here s < 31 < off(1)=35 -> p = 0, q = s.
    {
        const int s0 = c0 - 32 + lane;
        if (s0 >= 0) {
            const float2 a = zz[0];
            const float2 b = zz[s0];
            __stcs(orow + s0, a.x * b.x + a.y * b.y);
            if (s0 > 0)
                __stcs(orowi + s0, a.y * b.x - a.x * b.y);
        }
    }

    all_groups(typename make_iseq<NGRP>::type{}, zz, orow, orowi, c0, lane);
}

extern "C" void kernel_launch(void* const* d_in, const int* in_sizes, int n_in,
                              void* d_out, int out_size) {
    const float* z_re = (const float*)d_in[0];
    const float* z_im = (const float*)d_in[1];
    float* out = (float*)d_out;
    const int B = in_sizes[0] / NVAR;
    const int grid = (B + WPB - 1) / WPB;
    bihom_k3_kernel<<<grid, WPB * 32>>>(z_re, z_im, out, B);
}